// round 14
// baseline (speedup 1.0000x reference)
#include <cuda_runtime.h>
#include <cuda_bf16.h>
#include <cstdint>

#define N0c   100000
#define N1c   25000
#define N2c   5000
#define E0c   800000
#define E1c   160000
#define DIN   256
#define DHID  256
#define DOUT  128
#define EPSc  1e-5f
#define NEG_SLOPE 0.01f
#define MAXD  48

// ---------------- scratch (device globals) ----------------
__device__ float g_agg1[(size_t)N1c * DIN];
__device__ float g_h[(size_t)N1c * DHID];
__device__ float g_agg2[(size_t)N2c * DHID];
__device__ int   g_icnt1[N1c];
__device__ int   g_icnt2[N2c];
__device__ int   g_slot1[(size_t)N1c * MAXD];
__device__ int   g_slot2[(size_t)N2c * MAXD];

// ---------------- zero counters ----------------
__global__ void zero_counts() {
    int i = blockIdx.x * blockDim.x + threadIdx.x;
    int stride = gridDim.x * blockDim.x;
    for (int k = i; k < N1c; k += stride) g_icnt1[k] = 0;
    for (int k = i; k < N2c; k += stride) g_icnt2[k] = 0;
}

// ---------------- fused compact: layer0 blocks [0,3125), layer1 blocks [3125,3750) ----------------
__global__ void compact_both(const int* __restrict__ src0, const int* __restrict__ dst0,
                             const int* __restrict__ val0,
                             const int* __restrict__ src1, const int* __restrict__ dst1,
                             const int* __restrict__ val1,
                             const int* __restrict__ ts,
                             const int* __restrict__ time_p,
                             const int* __restrict__ interval_p,
                             float* __restrict__ mask_out) {
    int t0 = __ldg(time_p);
    int iv = __ldg(interval_p);
    if (blockIdx.x < E0c / 256) {
        int e = blockIdx.x * 256 + threadIdx.x;
        int t = __ldg(&ts[__ldg(&val0[e])]);
        bool m = (t >= t0) && (t < t0 + iv);
        if (!m) return;
        int d = __ldg(&dst0[e]);
        int p = atomicAdd(&g_icnt1[d], 1);
        if (p < MAXD) g_slot1[(size_t)d * MAXD + p] = __ldg(&src0[e]);
    } else {
        int e = (blockIdx.x - E0c / 256) * 256 + threadIdx.x;
        int t = __ldg(&ts[__ldg(&val1[e])]);
        bool m = (t >= t0) && (t < t0 + iv);
        if (mask_out != nullptr) mask_out[e] = m ? 1.0f : 0.0f;
        if (!m) return;
        int d = __ldg(&dst1[e]);
        int p = atomicAdd(&g_icnt2[d], 1);
        if (p < MAXD) g_slot2[(size_t)d * MAXD + p] = __ldg(&src1[e]);
    }
}

// ---------------- gather body: 2 warps per dst node, 4-edge unrolled ----------------
template <int LAYER>
__device__ __forceinline__ void gather_body(int gw, int lane, const float* __restrict__ feat) {
    constexpr int NR = (LAYER == 0) ? N1c : N2c;
    const int* cnt = (LAYER == 0) ? g_icnt1 : g_icnt2;
    const int* slot = (LAYER == 0) ? g_slot1 : g_slot2;
    const float* fsrc = (LAYER == 0) ? feat : (const float*)g_h;
    float* agg = (LAYER == 0) ? g_agg1 : g_agg2;

    int w = gw >> 1;
    int half = gw & 1;
    if (w >= NR) return;
    int off = half * 32 + lane;

    int deg = __ldg(&cnt[w]);
    int dc = (deg < MAXD) ? deg : MAXD;
    const int* sl = slot + (size_t)w * MAXD;

    float4 s = make_float4(0.f, 0.f, 0.f, 0.f);
    int e = 0;
    for (; e + 4 <= dc; e += 4) {
        int i0 = __ldg(&sl[e]);
        int i1 = __ldg(&sl[e + 1]);
        int i2 = __ldg(&sl[e + 2]);
        int i3 = __ldg(&sl[e + 3]);
        float4 a = __ldg(&((const float4*)(fsrc + (size_t)i0 * DHID))[off]);
        float4 b = __ldg(&((const float4*)(fsrc + (size_t)i1 * DHID))[off]);
        float4 c = __ldg(&((const float4*)(fsrc + (size_t)i2 * DHID))[off]);
        float4 d = __ldg(&((const float4*)(fsrc + (size_t)i3 * DHID))[off]);
        s.x += (a.x + b.x) + (c.x + d.x);
        s.y += (a.y + b.y) + (c.y + d.y);
        s.z += (a.z + b.z) + (c.z + d.z);
        s.w += (a.w + b.w) + (c.w + d.w);
    }
    for (; e < dc; e++) {
        int i0 = __ldg(&sl[e]);
        float4 a = __ldg(&((const float4*)(fsrc + (size_t)i0 * DHID))[off]);
        s.x += a.x; s.y += a.y; s.z += a.z; s.w += a.w;
    }
    float r = 1.0f / (float)((deg > 0) ? deg : 1);
    s.x *= r; s.y *= r; s.z *= r; s.w *= r;
    ((float4*)(agg + (size_t)w * DHID))[off] = s;
}

// ---------------- TF32 GEMM core (cp.async 2-stage) ----------------
__device__ __forceinline__ uint32_t f2tf(float f) {
    uint32_t u;
    asm("cvt.rna.tf32.f32 %0, %1;" : "=r"(u) : "f"(f));
    return u;
}

__device__ __forceinline__ void mma_tf32(float* c, const uint32_t* a, const uint32_t* b) {
    asm volatile(
        "mma.sync.aligned.m16n8k8.row.col.f32.tf32.tf32.f32 "
        "{%0,%1,%2,%3}, {%4,%5,%6,%7}, {%8,%9}, {%0,%1,%2,%3};"
        : "+f"(c[0]), "+f"(c[1]), "+f"(c[2]), "+f"(c[3])
        : "r"(a[0]), "r"(a[1]), "r"(a[2]), "r"(a[3]), "r"(b[0]), "r"(b[1]));
}

__device__ __forceinline__ void cp_async16(uint32_t dst, const void* src, int srcsize) {
    asm volatile("cp.async.cg.shared.global [%0], [%1], 16, %2;"
                 :: "r"(dst), "l"(src), "r"(srcsize));
}

// KT = number of 32-wide K tiles. SPLIT: A/B switch at KT/2. A row stride fixed 256.
template <int KT, int IM, int JN, bool SPLIT, bool LOADC, bool HASBIAS, bool DO_BN>
__device__ __forceinline__ void gemm_core(
    const float* __restrict__ A1, const float* __restrict__ A2,
    const float* __restrict__ B1, const float* __restrict__ B2,
    const float* __restrict__ bias,
    const float* __restrict__ gam, const float* __restrict__ bet,
    const float* __restrict__ rm, const float* __restrict__ rv,
    const float* __restrict__ Cin, float* __restrict__ Out,
    int M, int N, int bx, int by, float* sm) {
    constexpr int BM = IM * 32;
    constexpr int BN = JN * 32;
    constexpr int AS_STRIDE = 36;
    constexpr int BS_STRIDE = BN + 4;
    constexpr int ASZ = BM * AS_STRIDE;
    constexpr int BSZ = 32 * BS_STRIDE;
    constexpr int BUFSZ = ASZ + BSZ;
    constexpr int B4 = BN / 4;

    const int tid = threadIdx.x;
    const int lane = tid & 31;
    const int wid = tid >> 5;
    const int wm = wid >> 2;
    const int wn = wid & 3;
    const int bm = by * BM;
    const int bn = bx * BN;

    const uint32_t smbase = (uint32_t)__cvta_generic_to_shared(sm);

    auto load_tile = [&](int t, int buf) {
        const bool first = (!SPLIT) || (t < KT / 2);
        const float* Aptr = first ? A1 : A2;
        const float* Bptr = first ? B1 : B2;
        const int kk = SPLIT ? ((t * 32) & 255) : (t * 32);
        const uint32_t abase = smbase + (uint32_t)(buf * BUFSZ) * 4u;
        const uint32_t bbase = abase + (uint32_t)ASZ * 4u;
#pragma unroll
        for (int i = 0; i < IM; i++) {
            int idx = tid + i * 256;
            int m = idx >> 3, kg = idx & 7;
            int row = bm + m;
            int ok = (row < M) ? 16 : 0;
            int rc = (row < M) ? row : (M - 1);
            cp_async16(abase + (uint32_t)(m * AS_STRIDE + 4 * kg) * 4u,
                       Aptr + (size_t)rc * 256 + kk + 4 * kg, ok);
        }
#pragma unroll
        for (int i = 0; i < JN; i++) {
            int idx = tid + i * 256;
            int k = idx / B4, ng = idx % B4;
            cp_async16(bbase + (uint32_t)(k * BS_STRIDE + 4 * ng) * 4u,
                       Bptr + (size_t)(kk + k) * N + bn + 4 * ng, 16);
        }
        asm volatile("cp.async.commit_group;");
    };

    float acc[IM][JN][4];
#pragma unroll
    for (int i = 0; i < IM; i++)
#pragma unroll
        for (int j = 0; j < JN; j++)
#pragma unroll
            for (int r = 0; r < 4; r++) acc[i][j][r] = 0.0f;

    load_tile(0, 0);

    for (int t = 0; t < KT; t++) {
        if (t + 1 < KT) {
            load_tile(t + 1, (t + 1) & 1);
            asm volatile("cp.async.wait_group 1;");
        } else {
            asm volatile("cp.async.wait_group 0;");
        }
        __syncthreads();

        const float* As = sm + (t & 1) * BUFSZ;
        const float* Bs = As + ASZ;

#pragma unroll
        for (int ks = 0; ks < 4; ks++) {
            uint32_t af[IM][4], bf[JN][2];
            const int col = ks * 8 + (lane & 3);
            const int rbase = wm * (IM * 16) + (lane >> 2);
#pragma unroll
            for (int i = 0; i < IM; i++) {
                int r = rbase + i * 16;
                af[i][0] = f2tf(As[r * AS_STRIDE + col]);
                af[i][1] = f2tf(As[(r + 8) * AS_STRIDE + col]);
                af[i][2] = f2tf(As[r * AS_STRIDE + col + 4]);
                af[i][3] = f2tf(As[(r + 8) * AS_STRIDE + col + 4]);
            }
#pragma unroll
            for (int j = 0; j < JN; j++) {
                int n = wn * (JN * 8) + j * 8 + (lane >> 2);
                bf[j][0] = f2tf(Bs[col * BS_STRIDE + n]);
                bf[j][1] = f2tf(Bs[(col + 4) * BS_STRIDE + n]);
            }
#pragma unroll
            for (int i = 0; i < IM; i++)
#pragma unroll
                for (int j = 0; j < JN; j++) mma_tf32(acc[i][j], af[i], bf[j]);
        }
        __syncthreads();
    }

    float cb[JN][2], cs[JN][2], csh[JN][2];
#pragma unroll
    for (int j = 0; j < JN; j++) {
#pragma unroll
        for (int q = 0; q < 2; q++) {
            int c = bn + wn * (JN * 8) + j * 8 + 2 * (lane & 3) + q;
            cb[j][q] = HASBIAS ? bias[c] : 0.0f;
            if (DO_BN) {
                float s = gam[c] * rsqrtf(rv[c] + EPSc);
                cs[j][q] = s;
                csh[j][q] = bet[c] - rm[c] * s;
            }
        }
    }

#pragma unroll
    for (int i = 0; i < IM; i++) {
        int r0 = bm + wm * (IM * 16) + i * 16 + (lane >> 2);
#pragma unroll
        for (int j = 0; j < JN; j++) {
            int c = bn + wn * (JN * 8) + j * 8 + 2 * (lane & 3);
#pragma unroll
            for (int half = 0; half < 2; half++) {
                int r = r0 + half * 8;
                if (r >= M) continue;
                float y0 = acc[i][j][2 * half + 0] + cb[j][0];
                float y1 = acc[i][j][2 * half + 1] + cb[j][1];
                if (LOADC) {
                    float2 ci = *(const float2*)(Cin + (size_t)r * N + c);
                    y0 += ci.x;
                    y1 += ci.y;
                }
                if (DO_BN) {
                    y0 = y0 * cs[j][0] + csh[j][0];
                    y1 = y1 * cs[j][1] + csh[j][1];
                    y0 = (y0 >= 0.f) ? y0 : NEG_SLOPE * y0;
                    y1 = (y1 >= 0.f) ? y1 : NEG_SLOPE * y1;
                }
                float2 o = make_float2(y0, y1);
                *(float2*)(Out + (size_t)r * N + c) = o;
            }
        }
    }
}

#define GB1 392   // GEMM_root blocks: (256/128 N-tiles) x (196 M-tiles)
#define SMEMG ((128 * 36 + 32 * 132) * 2 * 4)
#define SMEM2 ((64 * 36 + 32 * 68) * 2 * 4)

// ---------------- K2: GEMM_root (x@W1r -> g_h raw) fused with gather0 ----------------
__global__ __launch_bounds__(256, 2) void k_root_gather(
    const float* __restrict__ x, const float* __restrict__ W1r) {
    extern __shared__ __align__(16) float sm[];
    if (blockIdx.x < GB1) {
        gemm_core<8, 4, 4, false, false, false, false>(
            x, nullptr, W1r, nullptr,
            nullptr, nullptr, nullptr, nullptr, nullptr,
            nullptr, g_h, N1c, DHID, blockIdx.x & 1, blockIdx.x >> 1, sm);
    } else {
        int gw = ((blockIdx.x - GB1) * 256 + threadIdx.x) >> 5;
        gather_body<0>(gw, threadIdx.x & 31, x);
    }
}

// ---------------- K3: GEMM_agg (agg1@W1l + b1 + g_h, BN, leaky -> g_h) ----------------
__global__ __launch_bounds__(256, 2) void k_gemm_agg(
    const float* __restrict__ W1l, const float* __restrict__ b1,
    const float* __restrict__ g1, const float* __restrict__ bt1,
    const float* __restrict__ rm1, const float* __restrict__ rv1) {
    extern __shared__ __align__(16) float sm[];
    gemm_core<8, 4, 4, false, true, true, true>(
        g_agg1, nullptr, W1l, nullptr,
        b1, g1, bt1, rm1, rv1,
        g_h, g_h, N1c, DHID, blockIdx.x, blockIdx.y, sm);
}

// ---------------- K4: gather1 ----------------
__global__ void k_gather1() {
    int gw = (blockIdx.x * blockDim.x + threadIdx.x) >> 5;
    gather_body<1>(gw, threadIdx.x & 31, nullptr);
}

// ---------------- K5: GEMM2 (agg2@W2l + h@W2r + b2 -> out) ----------------
__global__ __launch_bounds__(256, 2) void k_gemm2(
    const float* __restrict__ W2l, const float* __restrict__ W2r,
    const float* __restrict__ b2, float* __restrict__ out) {
    extern __shared__ __align__(16) float sm[];
    gemm_core<16, 2, 2, true, false, true, false>(
        g_agg2, (const float*)g_h, W2l, W2r,
        b2, nullptr, nullptr, nullptr, nullptr,
        nullptr, out, N2c, DOUT, blockIdx.x, blockIdx.y, sm);
}

// ---------------- launch ----------------
extern "C" void kernel_launch(void* const* d_in, const int* in_sizes, int n_in,
                              void* d_out, int out_size) {
    const float* x    = (const float*)d_in[0];
    const int* src0   = (const int*)d_in[1];
    const int* dst0   = (const int*)d_in[2];
    const int* val0   = (const int*)d_in[3];
    const int* src1   = (const int*)d_in[4];
    const int* dst1   = (const int*)d_in[5];
    const int* val1   = (const int*)d_in[6];
    const int* ts     = (const int*)d_in[7];
    const int* timep  = (const int*)d_in[8];
    const int* intvp  = (const int*)d_in[9];
    const float* W1l  = (const float*)d_in[10];
    const float* W1r  = (const float*)d_in[11];
    const float* b1   = (const float*)d_in[12];
    const float* g1   = (const float*)d_in[13];
    const float* bt1  = (const float*)d_in[14];
    const float* rm1  = (const float*)d_in[15];
    const float* rv1  = (const float*)d_in[16];
    const float* W2l  = (const float*)d_in[17];
    const float* W2r  = (const float*)d_in[18];
    const float* b2   = (const float*)d_in[19];

    float* out = (float*)d_out;
    float* mask_out = (out_size >= N2c * DOUT + E1c) ? (out + N2c * DOUT) : nullptr;

    static bool attr_done = false;
    if (!attr_done) {
        cudaFuncSetAttribute((const void*)k_root_gather,
                             cudaFuncAttributeMaxDynamicSharedMemorySize, SMEMG);
        cudaFuncSetAttribute((const void*)k_gemm_agg,
                             cudaFuncAttributeMaxDynamicSharedMemorySize, SMEMG);
        attr_done = true;
    }

    // 1) zero per-dst counters
    zero_counts<<<256, 256>>>();

    // 2) fused compact (layer0 + layer1 + mask1 output)
    compact_both<<<E0c / 256 + E1c / 256, 256>>>(src0, dst0, val0, src1, dst1, val1,
                                                 ts, timep, intvp, mask_out);

    // 3) GEMM_root1 (x@W1r, K=256) fused with gather0 (fills tail + idle slots)
    {
        int gather_blocks = (N1c * 64 + 255) / 256;  // 6250
        k_root_gather<<<GB1 + gather_blocks, 256, SMEMG>>>(x, W1r);
    }

    // 4) GEMM_agg1 (agg1@W1l + b1 + g_h, BN + leaky)
    k_gemm_agg<<<dim3(2, 196), 256, SMEMG>>>(W1l, b1, g1, bt1, rm1, rv1);

    // 5) gather1
    k_gather1<<<(N2c * 64 + 255) / 256, 256>>>();

    // 6) GEMM2
    k_gemm2<<<dim3(2, 79), 256, SMEM2>>>(W2l, W2r, b2, out);
}

// round 15
// speedup vs baseline: 1.3886x; 1.3886x over previous
#include <cuda_runtime.h>
#include <cuda_bf16.h>
#include <cstdint>

#define N0c   100000
#define N1c   25000
#define N2c   5000
#define E0c   800000
#define E1c   160000
#define DIN   256
#define DHID  256
#define DOUT  128
#define EPSc  1e-5f
#define NEG_SLOPE 0.01f
#define MAXD  48

// ---------------- scratch (device globals; zero-initialized at module load) ----------------
__device__ float g_agg1[(size_t)N1c * DIN];
__device__ float g_h[(size_t)N1c * DHID];
__device__ float g_agg2[(size_t)N2c * DHID];
__device__ __align__(16) int g_icnt1[N1c];   // invariant: ZERO at kernel_launch entry
__device__ __align__(16) int g_icnt2[N2c];   // (re-zeroed by GEMM2 tail blocks each call)
__device__ int g_slot1[(size_t)N1c * MAXD];
__device__ int g_slot2[(size_t)N2c * MAXD];

// ---------------- fused compact: layer0 blocks [0,3125), layer1 blocks [3125,3750) ----------------
__global__ void compact_both(const int* __restrict__ src0, const int* __restrict__ dst0,
                             const int* __restrict__ val0,
                             const int* __restrict__ src1, const int* __restrict__ dst1,
                             const int* __restrict__ val1,
                             const int* __restrict__ ts,
                             const int* __restrict__ time_p,
                             const int* __restrict__ interval_p,
                             float* __restrict__ mask_out) {
    int t0 = __ldg(time_p);
    int iv = __ldg(interval_p);
    if (blockIdx.x < E0c / 256) {
        int e = blockIdx.x * 256 + threadIdx.x;
        int t = __ldg(&ts[__ldg(&val0[e])]);
        bool m = (t >= t0) && (t < t0 + iv);
        if (!m) return;
        int d = __ldg(&dst0[e]);
        int p = atomicAdd(&g_icnt1[d], 1);
        if (p < MAXD) g_slot1[(size_t)d * MAXD + p] = __ldg(&src0[e]);
    } else {
        int e = (blockIdx.x - E0c / 256) * 256 + threadIdx.x;
        int t = __ldg(&ts[__ldg(&val1[e])]);
        bool m = (t >= t0) && (t < t0 + iv);
        if (mask_out != nullptr) mask_out[e] = m ? 1.0f : 0.0f;
        if (!m) return;
        int d = __ldg(&dst1[e]);
        int p = atomicAdd(&g_icnt2[d], 1);
        if (p < MAXD) g_slot2[(size_t)d * MAXD + p] = __ldg(&src1[e]);
    }
}

// ---------------- gather: 2 warps per dst node (half-row each), 4-edge unrolled ----------------
template <int LAYER>
__global__ void gather_mean(const float* __restrict__ feat) {
    constexpr int NR = (LAYER == 0) ? N1c : N2c;
    const int* cnt = (LAYER == 0) ? g_icnt1 : g_icnt2;
    const int* slot = (LAYER == 0) ? g_slot1 : g_slot2;
    const float* fsrc = (LAYER == 0) ? feat : (const float*)g_h;
    float* agg = (LAYER == 0) ? g_agg1 : g_agg2;

    int gw = (blockIdx.x * blockDim.x + threadIdx.x) >> 5;
    int w = gw >> 1;
    int half = gw & 1;
    if (w >= NR) return;
    int lane = threadIdx.x & 31;
    int off = half * 32 + lane;

    int deg = __ldg(&cnt[w]);
    int dc = (deg < MAXD) ? deg : MAXD;
    const int* sl = slot + (size_t)w * MAXD;

    float4 s = make_float4(0.f, 0.f, 0.f, 0.f);
    int e = 0;
    for (; e + 4 <= dc; e += 4) {
        int i0 = __ldg(&sl[e]);
        int i1 = __ldg(&sl[e + 1]);
        int i2 = __ldg(&sl[e + 2]);
        int i3 = __ldg(&sl[e + 3]);
        float4 a = __ldg(&((const float4*)(fsrc + (size_t)i0 * DHID))[off]);
        float4 b = __ldg(&((const float4*)(fsrc + (size_t)i1 * DHID))[off]);
        float4 c = __ldg(&((const float4*)(fsrc + (size_t)i2 * DHID))[off]);
        float4 d = __ldg(&((const float4*)(fsrc + (size_t)i3 * DHID))[off]);
        s.x += (a.x + b.x) + (c.x + d.x);
        s.y += (a.y + b.y) + (c.y + d.y);
        s.z += (a.z + b.z) + (c.z + d.z);
        s.w += (a.w + b.w) + (c.w + d.w);
    }
    for (; e < dc; e++) {
        int i0 = __ldg(&sl[e]);
        float4 a = __ldg(&((const float4*)(fsrc + (size_t)i0 * DHID))[off]);
        s.x += a.x; s.y += a.y; s.z += a.z; s.w += a.w;
    }
    float r = 1.0f / (float)((deg > 0) ? deg : 1);
    s.x *= r; s.y *= r; s.z *= r; s.w *= r;
    ((float4*)(agg + (size_t)w * DHID))[off] = s;
}

// ---------------- TF32 tensor-core GEMM, cp.async 2-stage (R7-exact numerics) ----------------
__device__ __forceinline__ uint32_t f2tf(float f) {
    uint32_t u;
    asm("cvt.rna.tf32.f32 %0, %1;" : "=r"(u) : "f"(f));
    return u;
}

__device__ __forceinline__ void mma_tf32(float* c, const uint32_t* a, const uint32_t* b) {
    asm volatile(
        "mma.sync.aligned.m16n8k8.row.col.f32.tf32.tf32.f32 "
        "{%0,%1,%2,%3}, {%4,%5,%6,%7}, {%8,%9}, {%0,%1,%2,%3};"
        : "+f"(c[0]), "+f"(c[1]), "+f"(c[2]), "+f"(c[3])
        : "r"(a[0]), "r"(a[1]), "r"(a[2]), "r"(a[3]), "r"(b[0]), "r"(b[1]));
}

__device__ __forceinline__ void cp_async16(uint32_t dst, const void* src, int srcsize) {
    asm volatile("cp.async.cg.shared.global [%0], [%1], 16, %2;"
                 :: "r"(dst), "l"(src), "r"(srcsize));
}

// Block tile: BM = IM*32, BN = JN*32, BK = 32; 8 warps (2m x 4n); 2-stage pipeline.
// TAILZERO (GEMM2 only): blocks with blockIdx.y >= 79 zero the compact counters
// for the NEXT kernel_launch call, then exit.
template <int LAYER, int IM, int JN, bool TAILZERO>
__global__ __launch_bounds__(256, 2) void gemm_tf32(
    const float* __restrict__ xroot,
    const float* __restrict__ B1, const float* __restrict__ B2,
    const float* __restrict__ bias,
    const float* __restrict__ gam, const float* __restrict__ bet,
    const float* __restrict__ rm, const float* __restrict__ rv,
    float* __restrict__ outp) {
    if (TAILZERO) {
        if (blockIdx.y >= 79) {
            int zb = (blockIdx.y - 79) * gridDim.x + blockIdx.x;
            int idx = zb * 256 + threadIdx.x;           // int4 index
            int4 z = make_int4(0, 0, 0, 0);
            if (idx < N1c / 4) ((int4*)g_icnt1)[idx] = z;
            else if (idx - N1c / 4 < N2c / 4) ((int4*)g_icnt2)[idx - N1c / 4] = z;
            return;
        }
    }

    constexpr int M = (LAYER == 1) ? N1c : N2c;
    constexpr int N = (LAYER == 1) ? DHID : DOUT;
    constexpr bool DO_BN = (LAYER == 1);
    constexpr int BM = IM * 32;
    constexpr int BN = JN * 32;
    constexpr int AS_STRIDE = 36;
    constexpr int BS_STRIDE = BN + 4;
    constexpr int ASZ = BM * AS_STRIDE;
    constexpr int BSZ = 32 * BS_STRIDE;
    constexpr int BUFSZ = ASZ + BSZ;
    constexpr int B4 = BN / 4;

    const float* Aagg  = (LAYER == 1) ? g_agg1 : g_agg2;
    const float* Aroot = (LAYER == 1) ? xroot : (const float*)g_h;
    float* Out = (LAYER == 1) ? g_h : outp;

    extern __shared__ __align__(16) float sm[];

    const int tid = threadIdx.x;
    const int lane = tid & 31;
    const int wid = tid >> 5;
    const int wm = wid >> 2;
    const int wn = wid & 3;
    const int bm = blockIdx.y * BM;
    const int bn = blockIdx.x * BN;

    const uint32_t smbase = (uint32_t)__cvta_generic_to_shared(sm);

    auto load_tile = [&](int t, int buf) {
        const bool ia = (t < 8);
        const float* Aptr = ia ? Aagg : Aroot;
        const float* Bptr = ia ? B1 : B2;
        const int kk = (t * 32) & 255;
        const uint32_t abase = smbase + (uint32_t)(buf * BUFSZ) * 4u;
        const uint32_t bbase = abase + (uint32_t)ASZ * 4u;
#pragma unroll
        for (int i = 0; i < IM; i++) {
            int idx = tid + i * 256;
            int m = idx >> 3, kg = idx & 7;
            int row = bm + m;
            int ok = (row < M) ? 16 : 0;
            int rc = (row < M) ? row : (M - 1);
            cp_async16(abase + (uint32_t)(m * AS_STRIDE + 4 * kg) * 4u,
                       Aptr + (size_t)rc * 256 + kk + 4 * kg, ok);
        }
#pragma unroll
        for (int i = 0; i < JN; i++) {
            int idx = tid + i * 256;
            int k = idx / B4, ng = idx % B4;
            cp_async16(bbase + (uint32_t)(k * BS_STRIDE + 4 * ng) * 4u,
                       Bptr + (size_t)(kk + k) * N + bn + 4 * ng, 16);
        }
        asm volatile("cp.async.commit_group;");
    };

    float acc[IM][JN][4];
#pragma unroll
    for (int i = 0; i < IM; i++)
#pragma unroll
        for (int j = 0; j < JN; j++)
#pragma unroll
            for (int r = 0; r < 4; r++) acc[i][j][r] = 0.0f;

    load_tile(0, 0);

    for (int t = 0; t < 16; t++) {
        if (t + 1 < 16) {
            load_tile(t + 1, (t + 1) & 1);
            asm volatile("cp.async.wait_group 1;");
        } else {
            asm volatile("cp.async.wait_group 0;");
        }
        __syncthreads();

        const float* As = sm + (t & 1) * BUFSZ;
        const float* Bs = As + ASZ;

#pragma unroll
        for (int ks = 0; ks < 4; ks++) {
            uint32_t af[IM][4], bf[JN][2];
            const int col = ks * 8 + (lane & 3);
            const int rbase = wm * (IM * 16) + (lane >> 2);
#pragma unroll
            for (int i = 0; i < IM; i++) {
                int r = rbase + i * 16;
                af[i][0] = f2tf(As[r * AS_STRIDE + col]);
                af[i][1] = f2tf(As[(r + 8) * AS_STRIDE + col]);
                af[i][2] = f2tf(As[r * AS_STRIDE + col + 4]);
                af[i][3] = f2tf(As[(r + 8) * AS_STRIDE + col + 4]);
            }
#pragma unroll
            for (int j = 0; j < JN; j++) {
                int n = wn * (JN * 8) + j * 8 + (lane >> 2);
                bf[j][0] = f2tf(Bs[col * BS_STRIDE + n]);
                bf[j][1] = f2tf(Bs[(col + 4) * BS_STRIDE + n]);
            }
#pragma unroll
            for (int i = 0; i < IM; i++)
#pragma unroll
                for (int j = 0; j < JN; j++) mma_tf32(acc[i][j], af[i], bf[j]);
        }
        __syncthreads();
    }

    float cb[JN][2], cs[JN][2], csh[JN][2];
#pragma unroll
    for (int j = 0; j < JN; j++) {
#pragma unroll
        for (int q = 0; q < 2; q++) {
            int c = bn + wn * (JN * 8) + j * 8 + 2 * (lane & 3) + q;
            cb[j][q] = bias[c];
            if (DO_BN) {
                float s = gam[c] * rsqrtf(rv[c] + EPSc);
                cs[j][q] = s;
                csh[j][q] = bet[c] - rm[c] * s;
            }
        }
    }

#pragma unroll
    for (int i = 0; i < IM; i++) {
        int r0 = bm + wm * (IM * 16) + i * 16 + (lane >> 2);
#pragma unroll
        for (int j = 0; j < JN; j++) {
            int c = bn + wn * (JN * 8) + j * 8 + 2 * (lane & 3);
#pragma unroll
            for (int half = 0; half < 2; half++) {
                int r = r0 + half * 8;
                if (r >= M) continue;
                float y0 = acc[i][j][2 * half + 0] + cb[j][0];
                float y1 = acc[i][j][2 * half + 1] + cb[j][1];
                if (DO_BN) {
                    y0 = y0 * cs[j][0] + csh[j][0];
                    y1 = y1 * cs[j][1] + csh[j][1];
                    y0 = (y0 >= 0.f) ? y0 : NEG_SLOPE * y0;
                    y1 = (y1 >= 0.f) ? y1 : NEG_SLOPE * y1;
                }
                float2 o = make_float2(y0, y1);
                *(float2*)(Out + (size_t)r * N + c) = o;
            }
        }
    }
}

#define SMEM1 ((128 * 36 + 32 * 132) * 2 * 4)
#define SMEM2 ((64 * 36 + 32 * 68) * 2 * 4)

// ---------------- launch (5 kernels) ----------------
extern "C" void kernel_launch(void* const* d_in, const int* in_sizes, int n_in,
                              void* d_out, int out_size) {
    const float* x    = (const float*)d_in[0];
    const int* src0   = (const int*)d_in[1];
    const int* dst0   = (const int*)d_in[2];
    const int* val0   = (const int*)d_in[3];
    const int* src1   = (const int*)d_in[4];
    const int* dst1   = (const int*)d_in[5];
    const int* val1   = (const int*)d_in[6];
    const int* ts     = (const int*)d_in[7];
    const int* timep  = (const int*)d_in[8];
    const int* intvp  = (const int*)d_in[9];
    const float* W1l  = (const float*)d_in[10];
    const float* W1r  = (const float*)d_in[11];
    const float* b1   = (const float*)d_in[12];
    const float* g1   = (const float*)d_in[13];
    const float* bt1  = (const float*)d_in[14];
    const float* rm1  = (const float*)d_in[15];
    const float* rv1  = (const float*)d_in[16];
    const float* W2l  = (const float*)d_in[17];
    const float* W2r  = (const float*)d_in[18];
    const float* b2   = (const float*)d_in[19];

    float* out = (float*)d_out;
    float* mask_out = (out_size >= N2c * DOUT + E1c) ? (out + N2c * DOUT) : nullptr;

    static bool attr_done = false;
    if (!attr_done) {
        cudaFuncSetAttribute((const void*)gemm_tf32<1, 4, 4, false>,
                             cudaFuncAttributeMaxDynamicSharedMemorySize, SMEM1);
        cudaFuncSetAttribute((const void*)gemm_tf32<2, 2, 2, true>,
                             cudaFuncAttributeMaxDynamicSharedMemorySize, SMEM2);
        attr_done = true;
    }

    // 1) fused compact (layer0 + layer1 + mask1 output); counters are zero on entry
    compact_both<<<E0c / 256 + E1c / 256, 256>>>(src0, dst0, val0, src1, dst1, val1,
                                                 ts, timep, intvp, mask_out);

    // 2) layer-0 gather + mean (2 warps per dst, 4-edge unrolled)
    gather_mean<0><<<(N1c * 64 + 255) / 256, 256>>>(x);

    // 3) GEMM1 (tf32, single K=512 pass) + bias + BN + leaky -> g_h
    gemm_tf32<1, 4, 4, false><<<dim3(2, 196), 256, SMEM1>>>(
        x, W1l, W1r, b1, g1, bt1, rm1, rv1, nullptr);

    // 4) layer-1 gather + mean
    gather_mean<1><<<(N2c * 64 + 255) / 256, 256>>>(nullptr);

    // 5) GEMM2 (K=512) + bias -> out; tail blocks (y >= 79) re-zero counters for next call
    gemm_tf32<2, 2, 2, true><<<dim3(2, 79 + 15), 256, SMEM2>>>(
        nullptr, W2l, W2r, b2, nullptr, nullptr, nullptr, nullptr, out);
}

// round 17
// speedup vs baseline: 1.8433x; 1.3274x over previous
#include <cuda_runtime.h>
#include <cuda_fp16.h>
#include <cstdint>

#define N0c   100000
#define N1c   25000
#define N2c   5000
#define E0c   800000
#define E1c   160000
#define EPSc  1e-5f
#define NEG_SLOPE 0.01f
#define MAXD  48

// ---------------- scratch (device globals; zero at module load) ----------------
// A operands: [row][512] half = [agg(256) | root(256)]
__device__ __half g_a1[(size_t)N1c * 512];   // agg1 | x_h
__device__ __half g_a2[(size_t)N2c * 512];   // agg2 | h
__device__ __half g_hh[(size_t)N1c * 256];   // full hidden (gather1 source)
// B operands transposed: [n][512] half = [Wl^T | Wr^T]
__device__ __half g_w1t[256 * 512];
__device__ __half g_w2t[128 * 512];
__device__ __align__(16) int g_icnt1[N1c];   // invariant: ZERO at kernel_launch entry
__device__ __align__(16) int g_icnt2[N2c];
__device__ int g_slot1[(size_t)N1c * MAXD];
__device__ int g_slot2[(size_t)N2c * MAXD];

// ---------------- K1: fused compact (both layers) + prep (x->half, W->half^T) ----------------
#define CB0 (E0c / 256)          // 3125
#define CB1 (E1c / 256)          // 625
#define XB  (N1c * 256 / 2048)   // 3125
#define TB  192
__global__ void compact_prep(const int* __restrict__ src0, const int* __restrict__ dst0,
                             const int* __restrict__ val0,
                             const int* __restrict__ src1, const int* __restrict__ dst1,
                             const int* __restrict__ val1,
                             const int* __restrict__ ts,
                             const int* __restrict__ time_p,
                             const int* __restrict__ interval_p,
                             float* __restrict__ mask_out,
                             const float* __restrict__ x,
                             const float* __restrict__ W1l, const float* __restrict__ W1r,
                             const float* __restrict__ W2l, const float* __restrict__ W2r) {
    __shared__ float tile[32][33];
    int b = blockIdx.x;
    int tid = threadIdx.x;
    if (b < CB0 + CB1) {
        int t0 = __ldg(time_p);
        int iv = __ldg(interval_p);
        if (b < CB0) {
            int e = b * 256 + tid;
            int t = __ldg(&ts[__ldg(&val0[e])]);
            if (!((t >= t0) && (t < t0 + iv))) return;
            int d = __ldg(&dst0[e]);
            int p = atomicAdd(&g_icnt1[d], 1);
            if (p < MAXD) g_slot1[(size_t)d * MAXD + p] = __ldg(&src0[e]);
        } else {
            int e = (b - CB0) * 256 + tid;
            int t = __ldg(&ts[__ldg(&val1[e])]);
            bool m = (t >= t0) && (t < t0 + iv);
            if (mask_out != nullptr) mask_out[e] = m ? 1.0f : 0.0f;
            if (!m) return;
            int d = __ldg(&dst1[e]);
            int p = atomicAdd(&g_icnt2[d], 1);
            if (p < MAXD) g_slot2[(size_t)d * MAXD + p] = __ldg(&src1[e]);
        }
    } else if (b < CB0 + CB1 + XB) {
        // x[:N1] fp32 -> half into g_a1 root half (cols 256..511)
        int gid = (b - CB0 - CB1) * 256 + tid;
        int f0 = gid * 8;
        int row = f0 >> 8, c = f0 & 255;
        float4 v0 = __ldg((const float4*)(x + f0));
        float4 v1 = __ldg((const float4*)(x + f0 + 4));
        __half2 h0 = __floats2half2_rn(v0.x, v0.y);
        __half2 h1 = __floats2half2_rn(v0.z, v0.w);
        __half2 h2 = __floats2half2_rn(v1.x, v1.y);
        __half2 h3 = __floats2half2_rn(v1.z, v1.w);
        uint4 u;
        u.x = *(uint32_t*)&h0; u.y = *(uint32_t*)&h1;
        u.z = *(uint32_t*)&h2; u.w = *(uint32_t*)&h3;
        *(uint4*)(g_a1 + (size_t)row * 512 + 256 + c) = u;
    } else {
        // weight transpose+convert: W[k][n] fp32 -> Wt[n][koff + k] half
        int tb = b - CB0 - CB1 - XB;
        const float* W; __half* Wt; int koff, Nn, tk, tn;
        if (tb < 64)       { W = W1l; Wt = g_w1t; koff = 0;   Nn = 256; tk = tb >> 3; tn = tb & 7; }
        else if (tb < 128) { tb -= 64;  W = W1r; Wt = g_w1t; koff = 256; Nn = 256; tk = tb >> 3; tn = tb & 7; }
        else if (tb < 160) { tb -= 128; W = W2l; Wt = g_w2t; koff = 0;   Nn = 128; tk = tb >> 2; tn = tb & 3; }
        else               { tb -= 160; W = W2r; Wt = g_w2t; koff = 256; Nn = 128; tk = tb >> 2; tn = tb & 3; }
        int k0 = tk * 32, n0 = tn * 32;
        {
            int kr = tid >> 3, nc = (tid & 7) * 4;
            float4 v = __ldg((const float4*)(W + (size_t)(k0 + kr) * Nn + n0 + nc));
            tile[kr][nc] = v.x; tile[kr][nc + 1] = v.y;
            tile[kr][nc + 2] = v.z; tile[kr][nc + 3] = v.w;
        }
        __syncthreads();
        {
            int nr = tid >> 3, kc = (tid & 7) * 4;
            __half2 p0 = __floats2half2_rn(tile[kc][nr], tile[kc + 1][nr]);
            __half2 p1 = __floats2half2_rn(tile[kc + 2][nr], tile[kc + 3][nr]);
            __half* dst = Wt + (size_t)(n0 + nr) * 512 + koff + k0 + kc;
            *(uint32_t*)dst = *(uint32_t*)&p0;
            *(uint32_t*)(dst + 2) = *(uint32_t*)&p1;
        }
    }
}

// ---------------- K2: gather0 (x fp32 -> agg1 half), 2 warps/dst, 4-edge unroll ----------------
__global__ void gather0(const float* __restrict__ x) {
    int gw = (blockIdx.x * blockDim.x + threadIdx.x) >> 5;
    int w = gw >> 1;
    if (w >= N1c) return;
    int lane = threadIdx.x & 31;
    int off = (gw & 1) * 32 + lane;   // float4 index in 256-float row

    int deg = __ldg(&g_icnt1[w]);
    int dc = (deg < MAXD) ? deg : MAXD;
    const int* sl = g_slot1 + (size_t)w * MAXD;

    float4 s = make_float4(0.f, 0.f, 0.f, 0.f);
    int e = 0;
    for (; e + 4 <= dc; e += 4) {
        int i0 = __ldg(&sl[e]), i1 = __ldg(&sl[e + 1]);
        int i2 = __ldg(&sl[e + 2]), i3 = __ldg(&sl[e + 3]);
        float4 a = __ldg(&((const float4*)(x + (size_t)i0 * 256))[off]);
        float4 b = __ldg(&((const float4*)(x + (size_t)i1 * 256))[off]);
        float4 c = __ldg(&((const float4*)(x + (size_t)i2 * 256))[off]);
        float4 d = __ldg(&((const float4*)(x + (size_t)i3 * 256))[off]);
        s.x += (a.x + b.x) + (c.x + d.x);
        s.y += (a.y + b.y) + (c.y + d.y);
        s.z += (a.z + b.z) + (c.z + d.z);
        s.w += (a.w + b.w) + (c.w + d.w);
    }
    for (; e < dc; e++) {
        int i0 = __ldg(&sl[e]);
        float4 a = __ldg(&((const float4*)(x + (size_t)i0 * 256))[off]);
        s.x += a.x; s.y += a.y; s.z += a.z; s.w += a.w;
    }
    float r = 1.0f / (float)((deg > 0) ? deg : 1);
    __half2 p0 = __floats2half2_rn(s.x * r, s.y * r);
    __half2 p1 = __floats2half2_rn(s.z * r, s.w * r);
    uint2 u; u.x = *(uint32_t*)&p0; u.y = *(uint32_t*)&p1;
    *(uint2*)(g_a1 + (size_t)w * 512 + off * 4) = u;
}

// ---------------- K4: gather1 (g_hh half -> agg2 half) ----------------
__global__ void gather1() {
    int gw = (blockIdx.x * blockDim.x + threadIdx.x) >> 5;
    int w = gw >> 1;
    if (w >= N2c) return;
    int lane = threadIdx.x & 31;
    int off = (gw & 1) * 32 + lane;   // 4-half group index in 256-half row

    int deg = __ldg(&g_icnt2[w]);
    int dc = (deg < MAXD) ? deg : MAXD;
    const int* sl = g_slot2 + (size_t)w * MAXD;

    float4 s = make_float4(0.f, 0.f, 0.f, 0.f);
    for (int e = 0; e < dc; e++) {
        int i0 = __ldg(&sl[e]);
        uint2 raw = __ldg((const uint2*)(g_hh + (size_t)i0 * 256 + off * 4));
        float2 f0 = __half22float2(*(__half2*)&raw.x);
        float2 f1 = __half22float2(*(__half2*)&raw.y);
        s.x += f0.x; s.y += f0.y; s.z += f1.x; s.w += f1.y;
    }
    float r = 1.0f / (float)((deg > 0) ? deg : 1);
    __half2 p0 = __floats2half2_rn(s.x * r, s.y * r);
    __half2 p1 = __floats2half2_rn(s.z * r, s.w * r);
    uint2 u; u.x = *(uint32_t*)&p0; u.y = *(uint32_t*)&p1;
    *(uint2*)(g_a2 + (size_t)w * 512 + off * 4) = u;
}

// ---------------- FP16 tensor-core GEMM (m16n8k16, fp32 acc), cp.async 2-stage ----------------
__device__ __forceinline__ void mma_f16(float* c, const uint32_t* a, const uint32_t* b) {
    asm volatile(
        "mma.sync.aligned.m16n8k16.row.col.f32.f16.f16.f32 "
        "{%0,%1,%2,%3}, {%4,%5,%6,%7}, {%8,%9}, {%0,%1,%2,%3};"
        : "+f"(c[0]), "+f"(c[1]), "+f"(c[2]), "+f"(c[3])
        : "r"(a[0]), "r"(a[1]), "r"(a[2]), "r"(a[3]), "r"(b[0]), "r"(b[1]));
}

__device__ __forceinline__ void cp_async16(uint32_t dst, const void* src, int srcsize) {
    asm volatile("cp.async.cg.shared.global [%0], [%1], 16, %2;"
                 :: "r"(dst), "l"(src), "r"(srcsize));
}

// A: [M][512] half (row stride 512). B: [Ntot][512] half. BK=32 halves per tile, KT=16.
// Smem rows padded to 40 halves (20 words) -> conflict-free fragment reads.
template <int LAYER, int IM, int JN, bool TAILZERO>
__global__ __launch_bounds__(256, 2) void gemm_f16(
    const float* __restrict__ bias,
    const float* __restrict__ gam, const float* __restrict__ bet,
    const float* __restrict__ rm, const float* __restrict__ rv,
    float* __restrict__ outp) {
    if (TAILZERO) {
        if (blockIdx.y >= 79) {
            int zb = (blockIdx.y - 79) * gridDim.x + blockIdx.x;
            int idx = zb * 256 + threadIdx.x;
            int4 z = make_int4(0, 0, 0, 0);
            if (idx < N1c / 4) ((int4*)g_icnt1)[idx] = z;
            else if (idx - N1c / 4 < N2c / 4) ((int4*)g_icnt2)[idx - N1c / 4] = z;
            return;
        }
    }

    constexpr int M = (LAYER == 1) ? N1c : N2c;
    constexpr bool DO_BN = (LAYER == 1);
    constexpr int BM = IM * 32;
    constexpr int BN = JN * 32;
    constexpr int AW = BM * 20;          // A words per buffer
    constexpr int BW = BN * 20;
    constexpr int BUF_H = (AW + BW) * 2; // halves per buffer
    constexpr int AITER = BM * 4 / 256;  // A: BM rows x 4 chunks / 256 threads
    constexpr int BITER = BN * 4 / 256;  // B: BN rows x 4 chunks / 256 threads

    const __half* A = (LAYER == 1) ? g_a1 : g_a2;
    const __half* B = (LAYER == 1) ? g_w1t : g_w2t;

    __shared__ __align__(16) __half sbuf[2 * BUF_H];

    const int tid = threadIdx.x;
    const int lane = tid & 31;
    const int wid = tid >> 5;
    const int wm = wid >> 2;
    const int wn = wid & 3;
    const int bm = blockIdx.y * BM;
    const int bn = blockIdx.x * BN;

    const uint32_t smbase = (uint32_t)__cvta_generic_to_shared(sbuf);

    auto load_tile = [&](int t, int buf) {
        const int kk = t * 32;
        const uint32_t abase = smbase + (uint32_t)(buf * BUF_H) * 2u;
        const uint32_t bbase = abase + (uint32_t)AW * 4u;
#pragma unroll
        for (int i = 0; i < AITER; i++) {
            int idx = tid + i * 256;
            int m = idx >> 2, kg = idx & 3;
            int row = bm + m;
            int ok = (row < M) ? 16 : 0;
            int rc = (row < M) ? row : (M - 1);
            cp_async16(abase + (uint32_t)(m * 40 + kg * 8) * 2u,
                       A + (size_t)rc * 512 + kk + kg * 8, ok);
        }
#pragma unroll
        for (int i = 0; i < BITER; i++) {
            int idx = tid + i * 256;
            int n = idx >> 2, kg = idx & 3;
            cp_async16(bbase + (uint32_t)(n * 40 + kg * 8) * 2u,
                       B + (size_t)(bn + n) * 512 + kk + kg * 8, 16);
        }
        asm volatile("cp.async.commit_group;");
    };

    float acc[IM][JN][4];
#pragma unroll
    for (int i = 0; i < IM; i++)
#pragma unroll
        for (int j = 0; j < JN; j++)
#pragma unroll
            for (int r = 0; r < 4; r++) acc[i][j][r] = 0.0f;

    load_tile(0, 0);

    for (int t = 0; t < 16; t++) {
        if (t + 1 < 16) {
            load_tile(t + 1, (t + 1) & 1);
            asm volatile("cp.async.wait_group 1;");
        } else {
            asm volatile("cp.async.wait_group 0;");
        }
        __syncthreads();

        const uint32_t* As32 = (const uint32_t*)(sbuf + (t & 1) * BUF_H);
        const uint32_t* Bs32 = As32 + AW;

#pragma unroll
        for (int ks = 0; ks < 2; ks++) {
            uint32_t af[IM][4], bf[JN][2];
            const int q = ks * 8 + (lane & 3);
            const int rbase = wm * (IM * 16) + (lane >> 2);
#pragma unroll
            for (int i = 0; i < IM; i++) {
                int r = rbase + i * 16;
                af[i][0] = As32[r * 20 + q];
                af[i][1] = As32[(r + 8) * 20 + q];
                af[i][2] = As32[r * 20 + q + 4];
                af[i][3] = As32[(r + 8) * 20 + q + 4];
            }
#pragma unroll
            for (int j = 0; j < JN; j++) {
                int n = wn * (JN * 8) + j * 8 + (lane >> 2);
                bf[j][0] = Bs32[n * 20 + q];
                bf[j][1] = Bs32[n * 20 + q + 4];
            }
#pragma unroll
            for (int i = 0; i < IM; i++)
#pragma unroll
                for (int j = 0; j < JN; j++) mma_f16(acc[i][j], af[i], bf[j]);
        }
        __syncthreads();
    }

    float cb[JN][2], cs[JN][2], csh[JN][2];
#pragma unroll
    for (int j = 0; j < JN; j++) {
#pragma unroll
        for (int q = 0; q < 2; q++) {
            int c = bn + wn * (JN * 8) + j * 8 + 2 * (lane & 3) + q;
            cb[j][q] = bias[c];
            if (DO_BN) {
                float s = gam[c] * rsqrtf(rv[c] + EPSc);
                cs[j][q] = s;
                csh[j][q] = bet[c] - rm[c] * s;
            }
        }
    }

#pragma unroll
    for (int i = 0; i < IM; i++) {
        int r0 = bm + wm * (IM * 16) + i * 16 + (lane >> 2);
#pragma unroll
        for (int j = 0; j < JN; j++) {
            int c = bn + wn * (JN * 8) + j * 8 + 2 * (lane & 3);
#pragma unroll
            for (int half = 0; half < 2; half++) {
                int r = r0 + half * 8;
                if (r >= M) continue;
                float y0 = acc[i][j][2 * half + 0] + cb[j][0];
                float y1 = acc[i][j][2 * half + 1] + cb[j][1];
                if (DO_BN) {
                    y0 = y0 * cs[j][0] + csh[j][0];
                    y1 = y1 * cs[j][1] + csh[j][1];
                    y0 = (y0 >= 0.f) ? y0 : NEG_SLOPE * y0;
                    y1 = (y1 >= 0.f) ? y1 : NEG_SLOPE * y1;
                    __half2 hv = __floats2half2_rn(y0, y1);
                    *(uint32_t*)(g_hh + (size_t)r * 256 + c) = *(uint32_t*)&hv;
                    if (r < N2c)
                        *(uint32_t*)(g_a2 + (size_t)r * 512 + 256 + c) = *(uint32_t*)&hv;
                } else {
                    *(float2*)(outp + (size_t)r * 128 + c) = make_float2(y0, y1);
                }
            }
        }
    }
}

// ---------------- launch (5 kernels) ----------------
extern "C" void kernel_launch(void* const* d_in, const int* in_sizes, int n_in,
                              void* d_out, int out_size) {
    const float* x    = (const float*)d_in[0];
    const int* src0   = (const int*)d_in[1];
    const int* dst0   = (const int*)d_in[2];
    const int* val0   = (const int*)d_in[3];
    const int* src1   = (const int*)d_in[4];
    const int* dst1   = (const int*)d_in[5];
    const int* val1   = (const int*)d_in[6];
    const int* ts     = (const int*)d_in[7];
    const int* timep  = (const int*)d_in[8];
    const int* intvp  = (const int*)d_in[9];
    const float* W1l  = (const float*)d_in[10];
    const float* W1r  = (const float*)d_in[11];
    const float* b1   = (const float*)d_in[12];
    const float* g1   = (const float*)d_in[13];
    const float* bt1  = (const float*)d_in[14];
    const float* rm1  = (const float*)d_in[15];
    const float* rv1  = (const float*)d_in[16];
    const float* W2l  = (const float*)d_in[17];
    const float* W2r  = (const float*)d_in[18];
    const float* b2   = (const float*)d_in[19];

    float* out = (float*)d_out;
    float* mask_out = (out_size >= N2c * 128 + E1c) ? (out + N2c * 128) : nullptr;

    // 1) fused compact(layer0+layer1+mask) + prep(x->half, weights->half^T)
    compact_prep<<<CB0 + CB1 + XB + TB, 256>>>(src0, dst0, val0, src1, dst1, val1,
                                               ts, timep, intvp, mask_out,
                                               x, W1l, W1r, W2l, W2r);

    // 2) gather0 -> agg1 half
    gather0<<<(N1c * 64) / 256, 256>>>(x);

    // 3) GEMM1 fp16 (A=[agg1|x], B=[W1l|W1r]^T) + bias + BN + leaky -> g_hh / g_a2-root
    gemm_f16<1, 4, 4, false><<<dim3(2, 196), 256>>>(b1, g1, bt1, rm1, rv1, nullptr);

    // 4) gather1 -> agg2 half
    gather1<<<(N2c * 64) / 256, 256>>>();

    // 5) GEMM2 fp16 + bias -> out (fp32); tail blocks re-zero counters for next replay
    gemm_f16<2, 2, 2, true><<<dim3(2, 79 + 15), 256>>>(b2, nullptr, nullptr, nullptr,
                                                       nullptr, out);
}